// round 7
// baseline (speedup 1.0000x reference)
#include <cuda_runtime.h>

// Problem constants
#define NB      4
#define NDET    128
#define NT      2048
#define NPIX    65536            // 256*256
#define DC      4                // dets per chunk (SMEM = DC*NT*16B = 128KB)
#define NCHUNK  32               // NDET / DC
#define G       2                // chunks accumulated per block
#define SLOTS   16               // NCHUNK / G
#define PT      16               // pixel tiles
#define PPT     4096             // NPIX / PT
#define THREADS 1024
#define PPTH    4                // pixels per thread = PPT / THREADS

// Scratch (static __device__ — no allocations allowed)
__device__ float4 g_part[SLOTS * NPIX];   // 16 MB partials [slot][pixel] -> per-batch

// ---------------------------------------------------------------------------
// Main backprojection kernel.
// grid = (PT, SLOTS) = 256 blocks x 1024 threads, 128 KB dynamic SMEM.
// Each block accumulates G=2 chunks in registers. Per chunk: stage 4 det
// rows (batch-transposed float4, from L2-resident 4 MB sino), sync, then
// each thread processes 4 pixels with software-pipelined lut prefetch
// (next pixel's 2 LDG.128 issued before current pixel's LDS gather chain).
// Deterministic (no atomics).
// ---------------------------------------------------------------------------
extern __shared__ float4 s_sino[];   // [DC][NT]  128 KB

__global__ void __launch_bounds__(THREADS, 1)
bp_main_kernel(const float* __restrict__ sino,
               const float4* __restrict__ lut4) {
    const int tid   = threadIdx.x;
    const int pbase = blockIdx.x * PPT;
    const int slot  = blockIdx.y;

    float4 acc[PPTH];
    #pragma unroll
    for (int pp = 0; pp < PPTH; pp++) acc[pp] = make_float4(0.f, 0.f, 0.f, 0.f);

    #pragma unroll
    for (int g = 0; g < G; g++) {
        const int c = slot * G + g;
        if (g > 0) __syncthreads();   // protect SMEM reuse

        // Stage DC det rows, transposing batches into float4 on the fly.
        #pragma unroll 8
        for (int i = tid; i < DC * NT; i += THREADS) {
            int j = i >> 11;            // det within chunk
            int k = i & (NT - 1);
            const float* sp = sino + (size_t)(c * DC + j) * NT + k;
            float4 v;
            v.x = __ldg(sp + 0 * NDET * NT);
            v.y = __ldg(sp + 1 * NDET * NT);
            v.z = __ldg(sp + 2 * NDET * NT);
            v.w = __ldg(sp + 3 * NDET * NT);
            s_sino[i] = v;
        }

        // Hann window weights for this chunk's 4 dets (norm at reduce).
        float apod[DC];
        #pragma unroll
        for (int j = 0; j < DC; j++) {
            int d = c * DC + j;
            apod[j] = 0.5f - 0.5f * cosf(6.2831853071795864769f * (float)d / 127.0f);
        }

        __syncthreads();

        // lut layout: [pixel][det][2] floats -> 64 float4 per pixel.
        // This chunk's 4 dets = 2 adjacent float4 (one aligned 32B sector).
        const float4* __restrict__ lp = lut4 + (size_t)pbase * 64 + (size_t)c * 2;

        // Prefetch pixel 0's lut.
        float4 la = __ldg(lp + (size_t)tid * 64);
        float4 lb = __ldg(lp + (size_t)tid * 64 + 1);

        #pragma unroll
        for (int pp = 0; pp < PPTH; pp++) {
            // Prefetch next pixel's lut before the gather chain.
            float4 na, nb;
            if (pp + 1 < PPTH) {
                size_t off = (size_t)((pp + 1) * THREADS + tid) * 64;
                na = __ldg(lp + off);
                nb = __ldg(lp + off + 1);
            }

            float kf[DC] = {la.x, la.z, lb.x, lb.z};
            float al[DC] = {la.y, la.w, lb.y, lb.w};

            #pragma unroll
            for (int j = 0; j < DC; j++) {
                int k = (int)kf[j];
                bool valid = ((unsigned)k < (unsigned)(NT - 1));  // 0 <= k < NT-1
                int k0 = min(max(k, 0), NT - 2);

                float4 s0 = s_sino[j * NT + k0];
                float4 s1 = s_sino[j * NT + k0 + 1];

                float w  = valid ? apod[j] : 0.0f;
                float wa = w * al[j];
                float w0 = w - wa;

                acc[pp].x = fmaf(w0, s0.x, fmaf(wa, s1.x, acc[pp].x));
                acc[pp].y = fmaf(w0, s0.y, fmaf(wa, s1.y, acc[pp].y));
                acc[pp].z = fmaf(w0, s0.z, fmaf(wa, s1.z, acc[pp].z));
                acc[pp].w = fmaf(w0, s0.w, fmaf(wa, s1.w, acc[pp].w));
            }

            la = na; lb = nb;
        }
    }

    float4* __restrict__ part = g_part + (size_t)slot * NPIX + pbase;
    #pragma unroll
    for (int pp = 0; pp < PPTH; pp++) {
        part[pp * THREADS + tid] = acc[pp];   // coalesced float4 store
    }
}

// ---------------------------------------------------------------------------
// Reduce partials over 16 slots, normalize, write output (B,1,NY,NX).
// Grouped full-unroll loads for MLP=8 per thread.
// ---------------------------------------------------------------------------
__global__ void __launch_bounds__(256)
bp_reduce_kernel(float* __restrict__ out) {
    int p = blockIdx.x * blockDim.x + threadIdx.x;
    if (p >= NPIX) return;

    float4 v[8];
    float4 acc = make_float4(0.f, 0.f, 0.f, 0.f);

    #pragma unroll
    for (int s = 0; s < 8; s++) v[s] = __ldg(&g_part[(size_t)s * NPIX + p]);
    #pragma unroll
    for (int s = 0; s < 8; s++) {
        acc.x += v[s].x; acc.y += v[s].y; acc.z += v[s].z; acc.w += v[s].w;
    }
    #pragma unroll
    for (int s = 0; s < 8; s++) v[s] = __ldg(&g_part[(size_t)(s + 8) * NPIX + p]);
    #pragma unroll
    for (int s = 0; s < 8; s++) {
        acc.x += v[s].x; acc.y += v[s].y; acc.z += v[s].z; acc.w += v[s].w;
    }

    // sum_d apod[d] = 64 - 0.5 * (geometric cos sum = 1) = 63.5 exactly
    const float inv_norm = 1.0f / 63.5f;
    out[0 * NPIX + p] = acc.x * inv_norm;
    out[1 * NPIX + p] = acc.y * inv_norm;
    out[2 * NPIX + p] = acc.z * inv_norm;
    out[3 * NPIX + p] = acc.w * inv_norm;
}

// ---------------------------------------------------------------------------
extern "C" void kernel_launch(void* const* d_in, const int* in_sizes, int n_in,
                              void* d_out, int out_size) {
    const float*  sino = (const float*)d_in[0];
    const float4* lut4 = (const float4*)d_in[1];
    float*        out  = (float*)d_out;

    cudaFuncSetAttribute(bp_main_kernel,
                         cudaFuncAttributeMaxDynamicSharedMemorySize,
                         DC * NT * (int)sizeof(float4));

    dim3 grid(PT, SLOTS);
    bp_main_kernel<<<grid, THREADS, DC * NT * sizeof(float4)>>>(sino, lut4);

    bp_reduce_kernel<<<(NPIX + 255) / 256, 256>>>(out);
}

// round 8
// speedup vs baseline: 1.4799x; 1.4799x over previous
#include <cuda_runtime.h>

// Problem constants
#define NB      4
#define NDET    128
#define NT      2048
#define NPIX    65536            // 256*256
#define DC      4                // dets per chunk (SMEM = DC*NT*16B = 128KB)
#define NCHUNK  32               // NDET / DC
#define PT      8                // pixel tiles
#define PPT     8192             // NPIX / PT
#define THREADS 1024
#define PPTH    8                // pixels per thread = PPT / THREADS

// Scratch (static __device__ — no allocations allowed)
__device__ float4 g_part[NCHUNK * NPIX];  // 32 MB partials [chunk][pixel] -> per-batch

// ---------------------------------------------------------------------------
// Main backprojection kernel (round-5 structure + lut software prefetch).
// grid = (PT, NCHUNK) = 256 blocks x 1024 threads, 128 KB dynamic SMEM.
// Each block: stage 4 det rows (batch-transposed float4 from L2-resident
// sino), one sync, then 8 pixels/thread. Next pixel's two lut LDG.128 are
// issued before the current pixel's LDS gather chain so the ~600-cycle DRAM
// latency overlaps SMEM work. acc is stored per pixel (low reg pressure).
// Deterministic (no atomics).
// ---------------------------------------------------------------------------
extern __shared__ float4 s_sino[];   // [DC][NT]  128 KB

__global__ void __launch_bounds__(THREADS, 1)
bp_main_kernel(const float* __restrict__ sino,
               const float4* __restrict__ lut4) {
    const int tid   = threadIdx.x;
    const int pbase = blockIdx.x * PPT;
    const int c     = blockIdx.y;          // det chunk

    // Stage DC det rows, transposing batches into float4 on the fly.
    #pragma unroll 8
    for (int i = tid; i < DC * NT; i += THREADS) {
        int j = i >> 11;            // det within chunk
        int k = i & (NT - 1);
        const float* sp = sino + (size_t)(c * DC + j) * NT + k;
        float4 v;
        v.x = __ldg(sp + 0 * NDET * NT);
        v.y = __ldg(sp + 1 * NDET * NT);
        v.z = __ldg(sp + 2 * NDET * NT);
        v.w = __ldg(sp + 3 * NDET * NT);
        s_sino[i] = v;
    }

    // Hann window weights for this chunk's 4 dets (norm at reduce).
    float apod[DC];
    #pragma unroll
    for (int j = 0; j < DC; j++) {
        int d = c * DC + j;
        apod[j] = 0.5f - 0.5f * cosf(6.2831853071795864769f * (float)d / 127.0f);
    }

    __syncthreads();

    // lut layout: [pixel][det][2] floats -> 64 float4 per pixel.
    // This chunk's 4 dets = 2 adjacent float4 (one aligned 32B sector).
    const float4* __restrict__ lp = lut4 + (size_t)pbase * 64 + (size_t)c * 2;
    float4* __restrict__ part = g_part + (size_t)c * NPIX + pbase;

    // Prefetch pixel 0's lut.
    float4 la = __ldg(lp + (size_t)tid * 64);
    float4 lb = __ldg(lp + (size_t)tid * 64 + 1);

    #pragma unroll
    for (int pp = 0; pp < PPTH; pp++) {
        // Issue next pixel's lut loads before the gather chain.
        float4 na = la, nb = lb;
        if (pp + 1 < PPTH) {
            size_t off = (size_t)((pp + 1) * THREADS + tid) * 64;
            na = __ldg(lp + off);
            nb = __ldg(lp + off + 1);
        }

        float kf[DC] = {la.x, la.z, lb.x, lb.z};
        float al[DC] = {la.y, la.w, lb.y, lb.w};

        float4 acc = make_float4(0.f, 0.f, 0.f, 0.f);

        #pragma unroll
        for (int j = 0; j < DC; j++) {
            int k = (int)kf[j];
            bool valid = ((unsigned)k < (unsigned)(NT - 1));  // 0 <= k < NT-1
            int k0 = min(max(k, 0), NT - 2);

            float4 s0 = s_sino[j * NT + k0];
            float4 s1 = s_sino[j * NT + k0 + 1];

            float w  = valid ? apod[j] : 0.0f;
            float wa = w * al[j];
            float w0 = w - wa;

            acc.x = fmaf(w0, s0.x, fmaf(wa, s1.x, acc.x));
            acc.y = fmaf(w0, s0.y, fmaf(wa, s1.y, acc.y));
            acc.z = fmaf(w0, s0.z, fmaf(wa, s1.z, acc.z));
            acc.w = fmaf(w0, s0.w, fmaf(wa, s1.w, acc.w));
        }

        part[pp * THREADS + tid] = acc;    // coalesced float4 store
        la = na; lb = nb;
    }
}

// ---------------------------------------------------------------------------
// Reduce: one thread per (pixel, batch) -> 262144 threads (4x occupancy of
// the old per-pixel version). 32 independent coalesced scalar loads each.
// ---------------------------------------------------------------------------
__global__ void __launch_bounds__(256)
bp_reduce_kernel(float* __restrict__ out) {
    int idx = blockIdx.x * blockDim.x + threadIdx.x;   // (pixel << 2) | batch
    if (idx >= NPIX * NB) return;
    int p = idx >> 2;
    int b = idx & 3;

    const float* __restrict__ pf = (const float*)g_part;   // [chunk][pixel][batch]

    float acc = 0.0f;
    #pragma unroll
    for (int c = 0; c < NCHUNK; c++) {
        acc += __ldg(pf + (size_t)c * (NPIX * 4) + (size_t)p * 4 + b);
    }

    // sum_d apod[d] = 64 - 0.5 * (geometric cos sum = 1) = 63.5 exactly
    out[(size_t)b * NPIX + p] = acc * (1.0f / 63.5f);
}

// ---------------------------------------------------------------------------
extern "C" void kernel_launch(void* const* d_in, const int* in_sizes, int n_in,
                              void* d_out, int out_size) {
    const float*  sino = (const float*)d_in[0];
    const float4* lut4 = (const float4*)d_in[1];
    float*        out  = (float*)d_out;

    cudaFuncSetAttribute(bp_main_kernel,
                         cudaFuncAttributeMaxDynamicSharedMemorySize,
                         DC * NT * (int)sizeof(float4));

    dim3 grid(PT, NCHUNK);
    bp_main_kernel<<<grid, THREADS, DC * NT * sizeof(float4)>>>(sino, lut4);

    bp_reduce_kernel<<<(NPIX * NB + 255) / 256, 256>>>(out);
}

// round 9
// speedup vs baseline: 1.6656x; 1.1255x over previous
#include <cuda_runtime.h>

// Problem constants
#define NB      4
#define NDET    128
#define NT      2048
#define NPIX    65536            // 256*256
#define DC      4                // dets per chunk (SMEM = DC*NT*16B = 128KB)
#define NCHUNK  32               // NDET / DC
#define PT      8                // pixel tiles
#define PPT     8192             // NPIX / PT
#define THREADS 1024
#define PPTH    8                // pixels per thread = PPT / THREADS

// ---------------------------------------------------------------------------
// Packed f32x2 helpers (Blackwell dual-FMA; only reachable via PTX).
// ---------------------------------------------------------------------------
__device__ __forceinline__ unsigned long long pk2(float lo, float hi) {
    unsigned long long r;
    asm("mov.b64 %0, {%1, %2};" : "=l"(r) : "f"(lo), "f"(hi));
    return r;
}
__device__ __forceinline__ void upk2(unsigned long long v, float& lo, float& hi) {
    asm("mov.b64 {%0, %1}, %2;" : "=f"(lo), "=f"(hi) : "l"(v));
}
__device__ __forceinline__ unsigned long long fma2(unsigned long long a,
                                                   unsigned long long b,
                                                   unsigned long long c) {
    unsigned long long d;
    asm("fma.rn.f32x2 %0, %1, %2, %3;" : "=l"(d) : "l"(a), "l"(b), "l"(c));
    return d;
}

// ---------------------------------------------------------------------------
// Zero-out kernel: d_out is poisoned before timing; atomics need zeros.
// ---------------------------------------------------------------------------
__global__ void __launch_bounds__(1024)
zero_out_kernel(float4* __restrict__ out) {
    int i = blockIdx.x * blockDim.x + threadIdx.x;
    if (i < NPIX) out[i] = make_float4(0.f, 0.f, 0.f, 0.f);   // NPIX*NB/4
}

// ---------------------------------------------------------------------------
// Main backprojection kernel.
// grid = (PT, NCHUNK) = 256 blocks x 1024 threads, 128 KB dynamic SMEM.
// Each block: stage 4 det rows (batch-transposed float4 from L2-resident
// sino), sync, then 8 pixels/thread with lut prefetch. Inner math uses
// fma.rn.f32x2 (16 FFMA2 instead of 32 FFMA per pixel-chunk). Results are
// accumulated directly into d_out via no-return float atomics (coalesced,
// 32 adds per address spread in time).
// ---------------------------------------------------------------------------
extern __shared__ float4 s_sino[];   // [DC][NT]  128 KB

__global__ void __launch_bounds__(THREADS, 1)
bp_main_kernel(const float* __restrict__ sino,
               const float4* __restrict__ lut4,
               float* __restrict__ out) {
    const int tid   = threadIdx.x;
    const int pbase = blockIdx.x * PPT;
    const int c     = blockIdx.y;          // det chunk

    // Stage DC det rows, transposing batches into float4 on the fly.
    #pragma unroll 8
    for (int i = tid; i < DC * NT; i += THREADS) {
        int j = i >> 11;            // det within chunk
        int k = i & (NT - 1);
        const float* sp = sino + (size_t)(c * DC + j) * NT + k;
        float4 v;
        v.x = __ldg(sp + 0 * NDET * NT);
        v.y = __ldg(sp + 1 * NDET * NT);
        v.z = __ldg(sp + 2 * NDET * NT);
        v.w = __ldg(sp + 3 * NDET * NT);
        s_sino[i] = v;
    }

    // Hann window weights, pre-divided by the exact norm (sum apod = 63.5).
    float apod[DC];
    #pragma unroll
    for (int j = 0; j < DC; j++) {
        int d = c * DC + j;
        apod[j] = (0.5f - 0.5f * cosf(6.2831853071795864769f * (float)d / 127.0f))
                  * (1.0f / 63.5f);
    }

    __syncthreads();

    // lut layout: [pixel][det][2] floats -> 64 float4 per pixel.
    // This chunk's 4 dets = 2 adjacent float4 (one aligned 32B sector).
    const float4* __restrict__ lp = lut4 + (size_t)pbase * 64 + (size_t)c * 2;

    // Prefetch pixel 0's lut.
    float4 la = __ldg(lp + (size_t)tid * 64);
    float4 lb = __ldg(lp + (size_t)tid * 64 + 1);

    #pragma unroll
    for (int pp = 0; pp < PPTH; pp++) {
        // Issue next pixel's lut loads before the gather chain.
        float4 na = la, nb = lb;
        if (pp + 1 < PPTH) {
            size_t off = (size_t)((pp + 1) * THREADS + tid) * 64;
            na = __ldg(lp + off);
            nb = __ldg(lp + off + 1);
        }

        float kf[DC] = {la.x, la.z, lb.x, lb.z};
        float al[DC] = {la.y, la.w, lb.y, lb.w};

        unsigned long long acc_xy = 0ull;   // packed (0.f, 0.f)
        unsigned long long acc_zw = 0ull;

        #pragma unroll
        for (int j = 0; j < DC; j++) {
            int k = (int)kf[j];
            bool valid = ((unsigned)k < (unsigned)(NT - 1));  // 0 <= k < NT-1
            int k0 = min(max(k, 0), NT - 2);

            float4 s0 = s_sino[j * NT + k0];
            float4 s1 = s_sino[j * NT + k0 + 1];

            float w  = valid ? apod[j] : 0.0f;
            float wa = w * al[j];
            float w0 = w - wa;

            unsigned long long w0p = pk2(w0, w0);
            unsigned long long wap = pk2(wa, wa);

            acc_xy = fma2(w0p, pk2(s0.x, s0.y), fma2(wap, pk2(s1.x, s1.y), acc_xy));
            acc_zw = fma2(w0p, pk2(s0.z, s0.w), fma2(wap, pk2(s1.z, s1.w), acc_zw));
        }

        float ax, ay, az, aw;
        upk2(acc_xy, ax, ay);
        upk2(acc_zw, az, aw);

        // Accumulate into out[batch][pixel]; coalesced across the warp,
        // result unused -> ptxas emits no-return REDG.
        const int p = pbase + pp * THREADS + tid;
        atomicAdd(out + 0 * NPIX + p, ax);
        atomicAdd(out + 1 * NPIX + p, ay);
        atomicAdd(out + 2 * NPIX + p, az);
        atomicAdd(out + 3 * NPIX + p, aw);

        la = na; lb = nb;
    }
}

// ---------------------------------------------------------------------------
extern "C" void kernel_launch(void* const* d_in, const int* in_sizes, int n_in,
                              void* d_out, int out_size) {
    const float*  sino = (const float*)d_in[0];
    const float4* lut4 = (const float4*)d_in[1];
    float*        out  = (float*)d_out;

    cudaFuncSetAttribute(bp_main_kernel,
                         cudaFuncAttributeMaxDynamicSharedMemorySize,
                         DC * NT * (int)sizeof(float4));

    zero_out_kernel<<<NPIX / 1024, 1024>>>((float4*)out);

    dim3 grid(PT, NCHUNK);
    bp_main_kernel<<<grid, THREADS, DC * NT * sizeof(float4)>>>(sino, lut4, out);
}